// round 3
// baseline (speedup 1.0000x reference)
#include <cuda_runtime.h>
#include <cstdint>

#define TSTEPS 512
#define BATCH  64
#define IDIM   256
#define HDIM   2048
#define NMT    16          // M tiles of H (2048/128)
#define NKG    9           // 8 K-slices of W_hat + 1 for W_in
#define NCTA   (NMT*NKG)   // 144 CTAs co-resident
#define KSL    256
#define NT     128         // h per CTA tile (mma N dim)
#define APAD   260         // padded SMEM row stride (conflict-free frags)
#define NTHR   256
#define BH     (BATCH*HDIM)        // 131072
#define SMEM_FLOATS (NT*APAD + BATCH*APAD)
#define SMEM_BYTES  (SMEM_FLOATS*4)   // 199680

__device__ float    g_state[3][BH];        // triple-buffered state [b][h]
__device__ float    g_part[2][NKG][BH];    // double-buffered partials [kg][b][h]
__device__ unsigned g_pflag[NCTA];         // produce flags (monotonic)
__device__ unsigned g_fflag[NCTA];         // finalize flags (monotonic)

__device__ __forceinline__ void mma_tf32(float* c, const uint32_t* a, const uint32_t* b) {
    asm volatile(
        "mma.sync.aligned.m16n8k8.row.col.f32.tf32.tf32.f32 "
        "{%0,%1,%2,%3}, {%4,%5,%6,%7}, {%8,%9}, {%0,%1,%2,%3};\n"
        : "+f"(c[0]), "+f"(c[1]), "+f"(c[2]), "+f"(c[3])
        : "r"(a[0]), "r"(a[1]), "r"(a[2]), "r"(a[3]), "r"(b[0]), "r"(b[1]));
}
__device__ __forceinline__ uint32_t rna_tf32(float f) {
    uint32_t u; asm("cvt.rna.tf32.f32 %0, %1;" : "=r"(u) : "f"(f)); return u;
}

__global__ void __launch_bounds__(NTHR, 1)
reservoir_kernel(const float* __restrict__ x,     // [T,B,I]
                 const float* __restrict__ s0,    // [B,H]
                 const float* __restrict__ Win,   // [H,I]
                 const float* __restrict__ What,  // [H,H]
                 float* __restrict__ out)         // [T,B,H]
{
    extern __shared__ float smem[];
    float* Ws = smem;              // [NT][APAD]    B operand: weight rows (n = h-local)
    float* As = smem + NT*APAD;    // [BATCH][APAD] A operand: state/x rows (m = batch)

    const int c   = blockIdx.x;
    const int tid = threadIdx.x;
    const int mt  = c % NMT;           // h tile [mt*128, mt*128+128)
    const int kg  = c / NMT;           // K group (8 = input projection)
    const int warp = tid >> 5, lane = tid & 31;
    const int gid  = lane >> 2, tig = lane & 3;
    const int wM   = (warp & 1) * 32;          // 2 warp-rows over M=64 (batch)
    const int wN   = (warp >> 1) * 32;         // 4 warp-cols over N=128 (h)

    const unsigned pbase = *(volatile unsigned*)&g_pflag[c];
    const unsigned fbase = *(volatile unsigned*)&g_fflag[c];

    // ---- one-time: weight slice -> SMEM (tf32 RNA) ----
    {
        const float* src; int stride;
        if (kg < 8) { src = What + (size_t)mt*NT*HDIM + (size_t)kg*KSL; stride = HDIM; }
        else        { src = Win  + (size_t)mt*NT*IDIM;                  stride = IDIM; }
        for (int i = tid; i < NT*64; i += NTHR) {          // 128 rows x 64 float4
            int r = i >> 6, c4 = i & 63;
            float4 v = *(const float4*)(src + (size_t)r*stride + c4*4);
            uint4 u;
            u.x = rna_tf32(v.x); u.y = rna_tf32(v.y); u.z = rna_tf32(v.z); u.w = rna_tf32(v.w);
            *(uint4*)(Ws + r*APAD + c4*4) = u;
        }
    }
    // ---- one-time: s0 -> state buffer 2 ----
    if (c < 128) {
        ((float4*)g_state[2])[c*256 + tid] = ((const float4*)s0)[c*256 + tid];
    }
    __syncthreads();
    if (tid == 0) {
        __threadfence();
        *(volatile unsigned*)&g_pflag[c] = pbase + 1;      // init arrival
    }
    if (tid < NCTA) {                                      // init barrier (all 144)
        while (*(volatile unsigned*)&g_pflag[tid] < pbase + 1) { }
    }
    __syncthreads();
    __threadfence();

    // finalize chunk bounds: e in [e0,e1) over 128x64 block (e = b*128 + h_local)
    const int e0 = (kg * (BATCH*NT)) / NKG;
    const int e1 = ((kg + 1) * (BATCH*NT)) / NKG;

    for (int t = 0; t < TSTEPS; ++t) {
        // ---- wait: state slice kg ready (18 finalizer CTAs); kg==8 needs only x ----
        if (kg < 8) {
            const unsigned tgt = fbase + (unsigned)t;      // t=0: trivially true
            if (tid < 2*NKG) {
                const int cc = (tid >> 1)*NMT + 2*kg + (tid & 1);
                while (*(volatile unsigned*)&g_fflag[cc] < tgt) { }
            }
            __syncthreads();
            __threadfence();
        }

        // ---- A tile: state slice (or x_t) -> SMEM, tf32 RNA ----
        {
            const float* src = (kg < 8) ? (g_state[(t+2)%3] + kg*KSL)
                                        : (x + (size_t)t*BATCH*IDIM);
            const int stride = (kg < 8) ? HDIM : IDIM;
            for (int i = tid; i < BATCH*64; i += NTHR) {   // 64 rows x 64 float4
                int r = i >> 6, c4 = i & 63;
                float4 v = *(const float4*)(src + (size_t)r*stride + c4*4);
                uint4 u;
                u.x = rna_tf32(v.x); u.y = rna_tf32(v.y); u.z = rna_tf32(v.z); u.w = rna_tf32(v.w);
                *(uint4*)(As + r*APAD + c4*4) = u;
            }
        }
        __syncthreads();

        // ---- MMA: D[64,128] = As[64,256] * Ws[128,256]^T (tf32) ----
        float acc[2][4][4];
        #pragma unroll
        for (int mi = 0; mi < 2; ++mi)
            #pragma unroll
            for (int ni = 0; ni < 4; ++ni)
                #pragma unroll
                for (int q = 0; q < 4; ++q) acc[mi][ni][q] = 0.f;

        #pragma unroll 4
        for (int kk = 0; kk < KSL; kk += 8) {
            uint32_t a[2][4], b[4][2];
            #pragma unroll
            for (int mi = 0; mi < 2; ++mi) {
                const float* ap = As + (wM + mi*16 + gid)*APAD + kk + tig;
                a[mi][0] = __float_as_uint(ap[0]);
                a[mi][1] = __float_as_uint(ap[8*APAD]);
                a[mi][2] = __float_as_uint(ap[4]);
                a[mi][3] = __float_as_uint(ap[8*APAD + 4]);
            }
            #pragma unroll
            for (int ni = 0; ni < 4; ++ni) {
                const float* bp = Ws + (wN + ni*8 + gid)*APAD + kk + tig;
                b[ni][0] = __float_as_uint(bp[0]);
                b[ni][1] = __float_as_uint(bp[4]);
            }
            #pragma unroll
            for (int mi = 0; mi < 2; ++mi)
                #pragma unroll
                for (int ni = 0; ni < 4; ++ni)
                    mma_tf32(acc[mi][ni], a[mi], b[ni]);
        }

        // ---- partials straight from accumulators: [b][h], sectored STG.64 ----
        {
            const int pb = t & 1;
            float* dst = &g_part[pb][kg][0] + mt*NT;
            #pragma unroll
            for (int mi = 0; mi < 2; ++mi) {
                #pragma unroll
                for (int ni = 0; ni < 4; ++ni) {
                    const int row = wM + mi*16 + gid;        // batch
                    const int col = wN + ni*8 + tig*2;       // h-local
                    *(float2*)(dst + (size_t)row*HDIM + col) =
                        make_float2(acc[mi][ni][0], acc[mi][ni][1]);
                    *(float2*)(dst + (size_t)(row+8)*HDIM + col) =
                        make_float2(acc[mi][ni][2], acc[mi][ni][3]);
                }
            }
        }
        __syncthreads();
        if (tid == 0) {
            __threadfence();
            *(volatile unsigned*)&g_pflag[c] = pbase + 2 + (unsigned)t;
        }

        // ---- wait: my mt-group's 9 partials ready ----
        {
            const unsigned tgt = pbase + 2 + (unsigned)t;
            if (tid < NKG) {
                const int cc = tid*NMT + mt;
                while (*(volatile unsigned*)&g_pflag[cc] < tgt) { }
            }
            __syncthreads();
            __threadfence();
        }

        // ---- finalize my chunk: sum 9 partials, tanh, leaky update, emit ----
        {
            const int pb = t & 1;
            const float* P = &g_part[pb][0][0];
            const float* sp = g_state[(t+2)%3];
            float*       sn = g_state[t%3];
            float*       op = out + (size_t)t*BH;
            for (int e = e0 + tid; e < e1; e += NTHR) {
                const int b = e >> 7;
                const int off = b*HDIM + mt*NT + (e & 127);
                float s = P[off];
                #pragma unroll
                for (int k2 = 1; k2 < NKG; ++k2) s += P[(size_t)k2*BH + off];
                const float ns = 0.5f*(sp[off] + tanhf(s));
                sn[off] = ns;
                op[off] = ns;
            }
        }
        __syncthreads();
        if (tid == 0) {
            __threadfence();
            *(volatile unsigned*)&g_fflag[c] = fbase + 1 + (unsigned)t;
        }
    }
}

extern "C" void kernel_launch(void* const* d_in, const int* in_sizes, int n_in,
                              void* d_out, int out_size)
{
    (void)in_sizes; (void)n_in; (void)out_size;
    const float* x    = (const float*)d_in[0];
    const float* s0   = (const float*)d_in[1];
    const float* Win  = (const float*)d_in[2];
    const float* What = (const float*)d_in[3];

    cudaFuncSetAttribute(reservoir_kernel,
                         cudaFuncAttributeMaxDynamicSharedMemorySize, SMEM_BYTES);
    reservoir_kernel<<<NCTA, NTHR, SMEM_BYTES>>>(x, s0, Win, What, (float*)d_out);
}

// round 4
// speedup vs baseline: 1.3331x; 1.3331x over previous
#include <cuda_runtime.h>
#include <cstdint>

#define TSTEPS 512
#define BATCH  64
#define IDIM   256
#define HDIM   2048
#define NMT    16          // h tiles (2048/128)
#define NKG    9           // 8 K-slices of W_hat + 1 for W_in
#define NCTA   (NMT*NKG)   // 144 CTAs co-resident
#define KSL    256
#define NT     128         // h per CTA tile
#define WPAD   260         // weight SMEM row stride (floats)
#define APAD   132         // A-half SMEM row stride (floats)
#define NTHR   512
#define BH     (BATCH*HDIM)
#define SMEM_BYTES ((NT*WPAD + 2*BATCH*APAD)*4)   // 200,704 B

__device__ float    g_state[3][BH];        // triple-buffered state [b][h]
__device__ float    g_part[2][NKG][BH];    // double-buffered partials [kg][b][h]
__device__ unsigned g_pflag[NCTA];         // produce flags (monotonic)
__device__ unsigned g_fflag[NCTA];         // finalize flags (monotonic)

__device__ __forceinline__ void mma_tf32(float* c, const uint32_t* a, const uint32_t* b) {
    asm volatile(
        "mma.sync.aligned.m16n8k8.row.col.f32.tf32.tf32.f32 "
        "{%0,%1,%2,%3}, {%4,%5,%6,%7}, {%8,%9}, {%0,%1,%2,%3};\n"
        : "+f"(c[0]), "+f"(c[1]), "+f"(c[2]), "+f"(c[3])
        : "r"(a[0]), "r"(a[1]), "r"(a[2]), "r"(a[3]), "r"(b[0]), "r"(b[1]));
}
__device__ __forceinline__ uint32_t rna_tf32(float f) {
    uint32_t u; asm("cvt.rna.tf32.f32 %0, %1;" : "=r"(u) : "f"(f)); return u;
}
__device__ __forceinline__ void relstore(unsigned* p, unsigned v) {
    asm volatile("st.release.gpu.global.u32 [%0], %1;" :: "l"(p), "r"(v) : "memory");
}
__device__ __forceinline__ unsigned acqload(const unsigned* p) {
    unsigned v;
    asm volatile("ld.acquire.gpu.global.u32 %0, [%1];" : "=r"(v) : "l"(p) : "memory");
    return v;
}
__device__ __forceinline__ void poll(const unsigned* p, unsigned tgt) {
    while ((int)(acqload(p) - tgt) < 0) { }
}

__global__ void __launch_bounds__(NTHR, 1)
reservoir_kernel(const float* __restrict__ x,     // [T,B,I]
                 const float* __restrict__ s0,    // [B,H]
                 const float* __restrict__ Win,   // [H,I]
                 const float* __restrict__ What,  // [H,H]
                 float* __restrict__ out)         // [T,B,H]
{
    extern __shared__ float smem[];
    float* Ws  = smem;                 // [NT][WPAD]    weight rows (n = h-local)
    float* As0 = smem + NT*WPAD;       // [BATCH][APAD] A half 0
    float* As1 = As0 + BATCH*APAD;     // [BATCH][APAD] A half 1

    const int c   = blockIdx.x;
    const int tid = threadIdx.x;
    const int mt  = c % NMT;
    const int kg  = c / NMT;           // 8 = input projection
    const int warp = tid >> 5, lane = tid & 31;
    const int gid  = lane >> 2, tig = lane & 3;
    const int wM   = (warp & 1) * 32;          // 2 warp-rows over M=64 (batch)
    const int wN   = (warp >> 1) * 16;         // 8 warp-cols over N=128 (h)

    const unsigned pbase = *(volatile unsigned*)&g_pflag[c];
    const unsigned fbase = *(volatile unsigned*)&g_fflag[c];

    // ---- one-time: weight slice -> SMEM (tf32 RNA) ----
    {
        const float* src; int stride;
        if (kg < 8) { src = What + (size_t)mt*NT*HDIM + (size_t)kg*KSL; stride = HDIM; }
        else        { src = Win  + (size_t)mt*NT*IDIM;                  stride = IDIM; }
        for (int i = tid; i < NT*64; i += NTHR) {          // 128 rows x 64 float4
            int r = i >> 6, c4 = i & 63;
            float4 v = *(const float4*)(src + (size_t)r*stride + c4*4);
            uint4 u;
            u.x = rna_tf32(v.x); u.y = rna_tf32(v.y); u.z = rna_tf32(v.z); u.w = rna_tf32(v.w);
            *(uint4*)(Ws + r*WPAD + c4*4) = u;
        }
    }
    // ---- one-time: s0 -> state buffer 2 ----
    if (c < 64) {
        ((float4*)g_state[2])[c*512 + tid] = ((const float4*)s0)[c*512 + tid];
    }
    __syncthreads();
    if (tid == 0) relstore(&g_pflag[c], pbase + 1);
    if (tid < NCTA) poll(&g_pflag[tid], pbase + 1);
    __syncthreads();

    // finalize chunk bounds: e in [e0,e1) over 64x128 block (e = b*128 + h_local)
    const int e0 = (kg * (BATCH*NT)) / NKG;
    const int e1 = ((kg + 1) * (BATCH*NT)) / NKG;

    for (int t = 0; t < TSTEPS; ++t) {
        // ---- wait: state slice kg ready (18 finalizer CTAs); kg==8 needs only x ----
        if (kg < 8 && tid < 2*NKG) {
            const int cc = (tid >> 1)*NMT + 2*kg + (tid & 1);
            poll(&g_fflag[cc], fbase + (unsigned)t);       // t=0 trivially true
        }
        __syncthreads();

        const float* src = (kg < 8) ? (g_state[(t+2)%3] + kg*KSL)
                                    : (x + (size_t)t*BATCH*IDIM);
        const int stride = (kg < 8) ? HDIM : IDIM;

        // ---- half 0: load, convert, stage ----
        float4 v[4];
        #pragma unroll
        for (int p = 0; p < 4; ++p) {
            int i = tid + p*NTHR, r = i >> 5, c4 = i & 31;
            v[p] = *(const float4*)(src + (size_t)r*stride + c4*4);
        }
        #pragma unroll
        for (int p = 0; p < 4; ++p) {
            int i = tid + p*NTHR, r = i >> 5, c4 = i & 31;
            uint4 u;
            u.x = rna_tf32(v[p].x); u.y = rna_tf32(v[p].y);
            u.z = rna_tf32(v[p].z); u.w = rna_tf32(v[p].w);
            *(uint4*)(As0 + r*APAD + c4*4) = u;
        }
        // ---- issue half-1 loads (overlap their latency with MMA half 0) ----
        float4 w[4];
        #pragma unroll
        for (int p = 0; p < 4; ++p) {
            int i = tid + p*NTHR, r = i >> 5, c4 = i & 31;
            w[p] = *(const float4*)(src + (size_t)r*stride + 128 + c4*4);
        }
        __syncthreads();

        float acc[2][2][4];
        #pragma unroll
        for (int mi = 0; mi < 2; ++mi)
            #pragma unroll
            for (int ni = 0; ni < 2; ++ni)
                #pragma unroll
                for (int q = 0; q < 4; ++q) acc[mi][ni][q] = 0.f;

        // ---- MMA half 0 (K cols 0..127) ----
        #pragma unroll 4
        for (int kk = 0; kk < 128; kk += 8) {
            uint32_t a[2][4], b[2][2];
            #pragma unroll
            for (int mi = 0; mi < 2; ++mi) {
                const float* ap = As0 + (wM + mi*16 + gid)*APAD + kk + tig;
                a[mi][0] = __float_as_uint(ap[0]);
                a[mi][1] = __float_as_uint(ap[8*APAD]);
                a[mi][2] = __float_as_uint(ap[4]);
                a[mi][3] = __float_as_uint(ap[8*APAD + 4]);
            }
            #pragma unroll
            for (int ni = 0; ni < 2; ++ni) {
                const float* bp = Ws + (wN + ni*8 + gid)*WPAD + kk + tig;
                b[ni][0] = __float_as_uint(bp[0]);
                b[ni][1] = __float_as_uint(bp[4]);
            }
            #pragma unroll
            for (int mi = 0; mi < 2; ++mi)
                #pragma unroll
                for (int ni = 0; ni < 2; ++ni)
                    mma_tf32(acc[mi][ni], a[mi], b[ni]);
        }

        // ---- stage half 1 ----
        #pragma unroll
        for (int p = 0; p < 4; ++p) {
            int i = tid + p*NTHR, r = i >> 5, c4 = i & 31;
            uint4 u;
            u.x = rna_tf32(w[p].x); u.y = rna_tf32(w[p].y);
            u.z = rna_tf32(w[p].z); u.w = rna_tf32(w[p].w);
            *(uint4*)(As1 + r*APAD + c4*4) = u;
        }
        __syncthreads();

        // ---- MMA half 1 (K cols 128..255) ----
        #pragma unroll 4
        for (int kk = 0; kk < 128; kk += 8) {
            uint32_t a[2][4], b[2][2];
            #pragma unroll
            for (int mi = 0; mi < 2; ++mi) {
                const float* ap = As1 + (wM + mi*16 + gid)*APAD + kk + tig;
                a[mi][0] = __float_as_uint(ap[0]);
                a[mi][1] = __float_as_uint(ap[8*APAD]);
                a[mi][2] = __float_as_uint(ap[4]);
                a[mi][3] = __float_as_uint(ap[8*APAD + 4]);
            }
            #pragma unroll
            for (int ni = 0; ni < 2; ++ni) {
                const float* bp = Ws + (wN + ni*8 + gid)*WPAD + 128 + kk + tig;
                b[ni][0] = __float_as_uint(bp[0]);
                b[ni][1] = __float_as_uint(bp[4]);
            }
            #pragma unroll
            for (int mi = 0; mi < 2; ++mi)
                #pragma unroll
                for (int ni = 0; ni < 2; ++ni)
                    mma_tf32(acc[mi][ni], a[mi], b[ni]);
        }

        // ---- partials straight from accumulators: [b][h] ----
        {
            const int pb = t & 1;
            float* dst = &g_part[pb][kg][0] + mt*NT;
            #pragma unroll
            for (int mi = 0; mi < 2; ++mi) {
                #pragma unroll
                for (int ni = 0; ni < 2; ++ni) {
                    const int row = wM + mi*16 + gid;        // batch
                    const int col = wN + ni*8 + tig*2;       // h-local
                    *(float2*)(dst + (size_t)row*HDIM + col) =
                        make_float2(acc[mi][ni][0], acc[mi][ni][1]);
                    *(float2*)(dst + (size_t)(row+8)*HDIM + col) =
                        make_float2(acc[mi][ni][2], acc[mi][ni][3]);
                }
            }
        }
        __syncthreads();
        if (tid == 0) relstore(&g_pflag[c], pbase + 2 + (unsigned)t);

        // ---- wait: my mt-group's 9 partials ready ----
        if (tid < NKG) poll(&g_pflag[tid*NMT + mt], pbase + 2 + (unsigned)t);
        __syncthreads();

        // ---- finalize my chunk: sum 9 partials, tanh, leaky update ----
        float ns0 = 0.f, ns1 = 0.f;
        int   off0 = -1,  off1 = -1;
        {
            const int pb = t & 1;
            const float* P  = &g_part[pb][0][0];
            const float* sp = g_state[(t+2)%3];
            float*       sn = g_state[t%3];

            int e = e0 + tid;
            if (e < e1) {
                const int b = e >> 7;
                off0 = b*HDIM + mt*NT + (e & 127);
                float s = P[off0];
                #pragma unroll
                for (int k2 = 1; k2 < NKG; ++k2) s += P[(size_t)k2*BH + off0];
                ns0 = 0.5f*(sp[off0] + tanhf(s));
                sn[off0] = ns0;
            }
            e += NTHR;
            if (e < e1) {
                const int b = e >> 7;
                off1 = b*HDIM + mt*NT + (e & 127);
                float s = P[off1];
                #pragma unroll
                for (int k2 = 1; k2 < NKG; ++k2) s += P[(size_t)k2*BH + off1];
                ns1 = 0.5f*(sp[off1] + tanhf(s));
                sn[off1] = ns1;
            }
        }
        __syncthreads();
        if (tid == 0) relstore(&g_fflag[c], fbase + 1 + (unsigned)t);

        // ---- output writes off the critical chain ----
        {
            float* op = out + (size_t)t*BH;
            if (off0 >= 0) op[off0] = ns0;
            if (off1 >= 0) op[off1] = ns1;
        }
    }
}

extern "C" void kernel_launch(void* const* d_in, const int* in_sizes, int n_in,
                              void* d_out, int out_size)
{
    (void)in_sizes; (void)n_in; (void)out_size;
    const float* x    = (const float*)d_in[0];
    const float* s0   = (const float*)d_in[1];
    const float* Win  = (const float*)d_in[2];
    const float* What = (const float*)d_in[3];

    cudaFuncSetAttribute(reservoir_kernel,
                         cudaFuncAttributeMaxDynamicSharedMemorySize, SMEM_BYTES);
    reservoir_kernel<<<NCTA, NTHR, SMEM_BYTES>>>(x, s0, Win, What, (float*)d_out);
}

// round 6
// speedup vs baseline: 2.1896x; 1.6425x over previous
#include <cuda_runtime.h>
#include <cstdint>

#define TSTEPS 512
#define BATCH  64
#define HB     32          // half-batch stream size
#define IDIM   256
#define HDIM   2048
#define NMT    16          // h tiles (2048/128)
#define NKG    9           // 8 K-slices of W_hat + 1 for W_in
#define NCTA   (NMT*NKG)   // 144 CTAs co-resident
#define KSL    256
#define NT     128         // h per CTA tile
#define WPAD   260
#define APAD   260
#define NTHR   256
#define BH     (BATCH*HDIM)
#define HBH    (HB*HDIM)
#define SMEM_BYTES ((NT*WPAD + HB*APAD)*4)   // 166,400 B

__device__ float    g_state[3][BH];            // triple-buffered state [b][h]
__device__ float    g_part[2][3][NKG][HBH];    // [half][buf(t%3)][kg][b_local*HDIM+h]
__device__ unsigned g_pflag[2][NCTA];          // produce flags per half (monotonic)
__device__ unsigned g_fflag[2][NCTA];          // finalize flags per half (monotonic)

__device__ __forceinline__ void mma_tf32(float* c, const uint32_t* a, const uint32_t* b) {
    asm volatile(
        "mma.sync.aligned.m16n8k8.row.col.f32.tf32.tf32.f32 "
        "{%0,%1,%2,%3}, {%4,%5,%6,%7}, {%8,%9}, {%0,%1,%2,%3};\n"
        : "+f"(c[0]), "+f"(c[1]), "+f"(c[2]), "+f"(c[3])
        : "r"(a[0]), "r"(a[1]), "r"(a[2]), "r"(a[3]), "r"(b[0]), "r"(b[1]));
}
__device__ __forceinline__ uint32_t rna_tf32(float f) {
    uint32_t u; asm("cvt.rna.tf32.f32 %0, %1;" : "=r"(u) : "f"(f)); return u;
}
__device__ __forceinline__ void relstore(unsigned* p, unsigned v) {
    asm volatile("st.release.gpu.global.u32 [%0], %1;" :: "l"(p), "r"(v) : "memory");
}
__device__ __forceinline__ unsigned acqload(const unsigned* p) {
    unsigned v;
    asm volatile("ld.acquire.gpu.global.u32 %0, [%1];" : "=r"(v) : "l"(p) : "memory");
    return v;
}
__device__ __forceinline__ void poll(const unsigned* p, unsigned tgt) {
    while ((int)(acqload(p) - tgt) < 0) { }
}

__global__ void __launch_bounds__(NTHR, 1)
reservoir_kernel(const float* __restrict__ x,     // [T,B,I]
                 const float* __restrict__ s0,    // [B,H]
                 const float* __restrict__ Win,   // [H,I]
                 const float* __restrict__ What,  // [H,H]
                 float* __restrict__ out)         // [T,B,H]
{
    extern __shared__ float smem[];
    float* Ws = smem;                 // [NT][WPAD]  weight rows (n = h-local)
    float* As = smem + NT*WPAD;       // [HB][APAD]  A tile (reused per stream)

    const int c   = blockIdx.x;
    const int tid = threadIdx.x;
    const int mt  = c % NMT;
    const int kg  = c / NMT;           // 8 = input projection
    const int warp = tid >> 5, lane = tid & 31;
    const int gid  = lane >> 2, tig = lane & 3;
    const int wm   = (warp & 1) * 16;          // 2 warp-rows over M=32 (batch)
    const int wn   = (warp >> 1) * 32;         // 4 warp-cols over N=128 (h)

    const unsigned pb0 = *(volatile unsigned*)&g_pflag[0][c];
    const unsigned pb1 = *(volatile unsigned*)&g_pflag[1][c];
    const unsigned fb0 = *(volatile unsigned*)&g_fflag[0][c];
    const unsigned fb1 = *(volatile unsigned*)&g_fflag[1][c];

    // ---- one-time: weight slice -> SMEM (tf32 RNA) ----
    {
        const float* src; int stride;
        if (kg < 8) { src = What + (size_t)mt*NT*HDIM + (size_t)kg*KSL; stride = HDIM; }
        else        { src = Win  + (size_t)mt*NT*IDIM;                  stride = IDIM; }
        for (int i = tid; i < NT*64; i += NTHR) {
            int r = i >> 6, c4 = i & 63;
            float4 v = *(const float4*)(src + (size_t)r*stride + c4*4);
            uint4 u;
            u.x = rna_tf32(v.x); u.y = rna_tf32(v.y); u.z = rna_tf32(v.z); u.w = rna_tf32(v.w);
            *(uint4*)(Ws + r*WPAD + c4*4) = u;
        }
    }
    // ---- one-time: s0 -> state buffer 2 ----
    if (c < 128) {
        ((float4*)g_state[2])[c*256 + tid] = ((const float4*)s0)[c*256 + tid];
    }
    __syncthreads();
    if (tid == 0) relstore(&g_pflag[0][c], pb0 + 1);
    if (tid < NCTA) poll(&g_pflag[0][tid], pb0 + 1);
    __syncthreads();

    // finalize chunk bounds over [HB x NT] block (e = b_local*128 + h_local)
    const int e0 = (kg * (HB*NT)) / NKG;
    const int e1 = ((kg + 1) * (HB*NT)) / NKG;

    for (int t = 0; t < TSTEPS; ++t) {
        const int pbuf = t % 3;

        // ================= produce: stream h = 0, then 1 =================
        for (int h = 0; h < 2; ++h) {
            const unsigned ftgt = (h ? fb1 : fb0) + (unsigned)t;   // t=0 trivially true
            const unsigned ptgt = (h ? pb1 + 1 : pb0 + 2) + (unsigned)t;

            // HARDENED: wait on ALL finalizers of this half from step t-1
            if (kg < 8 && tid < NCTA) poll(&g_fflag[h][tid], ftgt);
            __syncthreads();

            // ---- A tile: state half-slice (or x_t half) -> regs -> SMEM ----
            const float* src = (kg < 8) ? (g_state[(t+2)%3] + (size_t)h*HB*HDIM + kg*KSL)
                                        : (x + (size_t)t*BATCH*IDIM + (size_t)h*HB*IDIM);
            const int stride = (kg < 8) ? HDIM : IDIM;
            float4 v[8];
            #pragma unroll
            for (int p = 0; p < 8; ++p) {
                int i = tid + p*NTHR, r = i >> 6, c4 = i & 63;
                v[p] = *(const float4*)(src + (size_t)r*stride + c4*4);
            }
            #pragma unroll
            for (int p = 0; p < 8; ++p) {
                int i = tid + p*NTHR, r = i >> 6, c4 = i & 63;
                uint4 u;
                u.x = rna_tf32(v[p].x); u.y = rna_tf32(v[p].y);
                u.z = rna_tf32(v[p].z); u.w = rna_tf32(v[p].w);
                *(uint4*)(As + r*APAD + c4*4) = u;
            }
            __syncthreads();

            // ---- MMA: D[32,128] = As[32,256] * Ws[128,256]^T ----
            float acc[4][4];
            #pragma unroll
            for (int ni = 0; ni < 4; ++ni)
                #pragma unroll
                for (int q = 0; q < 4; ++q) acc[ni][q] = 0.f;

            #pragma unroll 4
            for (int kk = 0; kk < KSL; kk += 8) {
                uint32_t a[4], b[4][2];
                const float* ap = As + (wm + gid)*APAD + kk + tig;
                a[0] = __float_as_uint(ap[0]);
                a[1] = __float_as_uint(ap[8*APAD]);
                a[2] = __float_as_uint(ap[4]);
                a[3] = __float_as_uint(ap[8*APAD + 4]);
                #pragma unroll
                for (int ni = 0; ni < 4; ++ni) {
                    const float* bp = Ws + (wn + ni*8 + gid)*WPAD + kk + tig;
                    b[ni][0] = __float_as_uint(bp[0]);
                    b[ni][1] = __float_as_uint(bp[4]);
                }
                #pragma unroll
                for (int ni = 0; ni < 4; ++ni)
                    mma_tf32(acc[ni], a, b[ni]);
            }
            __syncthreads();   // done reading As before next stream overwrites

            // ---- partial store [b_local][h] ----
            {
                float* dst = &g_part[h][pbuf][kg][0] + mt*NT;
                #pragma unroll
                for (int ni = 0; ni < 4; ++ni) {
                    const int row = wm + gid;
                    const int col = wn + ni*8 + tig*2;
                    *(float2*)(dst + (size_t)row*HDIM + col) =
                        make_float2(acc[ni][0], acc[ni][1]);
                    *(float2*)(dst + (size_t)(row+8)*HDIM + col) =
                        make_float2(acc[ni][2], acc[ni][3]);
                }
            }
            __syncthreads();
            if (tid == 0) relstore(&g_pflag[h][c], ptgt);
        }

        // ================= finalize: stream h = 0, then 1 =================
        for (int h = 0; h < 2; ++h) {
            const unsigned ptgt = (h ? pb1 + 1 : pb0 + 2) + (unsigned)t;
            // HARDENED: wait on ALL producers of this half from step t
            if (tid < NCTA) poll(&g_pflag[h][tid], ptgt);
            __syncthreads();

            {
                const float* P  = &g_part[h][pbuf][0][0];
                const float* sp = g_state[(t+2)%3];
                float*       sn = g_state[t%3];
                float*       op = out + (size_t)t*BH;

                int e = e0 + tid;
                if (e < e1) {
                    const int bl = e >> 7;
                    const int off = bl*HDIM + mt*NT + (e & 127);
                    float s = P[off];
                    #pragma unroll
                    for (int k2 = 1; k2 < NKG; ++k2) s += P[(size_t)k2*HBH + off];
                    const int so = (h*HB + bl)*HDIM + mt*NT + (e & 127);
                    const float ns = 0.5f*(sp[so] + tanhf(s));
                    sn[so] = ns;
                    op[so] = ns;
                }
                e += NTHR;
                if (e < e1) {
                    const int bl = e >> 7;
                    const int off = bl*HDIM + mt*NT + (e & 127);
                    float s = P[off];
                    #pragma unroll
                    for (int k2 = 1; k2 < NKG; ++k2) s += P[(size_t)k2*HBH + off];
                    const int so = (h*HB + bl)*HDIM + mt*NT + (e & 127);
                    const float ns = 0.5f*(sp[so] + tanhf(s));
                    sn[so] = ns;
                    op[so] = ns;
                }
            }
            __syncthreads();
            if (tid == 0) relstore(&g_fflag[h][c], (h ? fb1 : fb0) + 1 + (unsigned)t);
        }
    }
}

extern "C" void kernel_launch(void* const* d_in, const int* in_sizes, int n_in,
                              void* d_out, int out_size)
{
    (void)in_sizes; (void)n_in; (void)out_size;
    const float* x    = (const float*)d_in[0];
    const float* s0   = (const float*)d_in[1];
    const float* Win  = (const float*)d_in[2];
    const float* What = (const float*)d_in[3];

    cudaFuncSetAttribute(reservoir_kernel,
                         cudaFuncAttributeMaxDynamicSharedMemorySize, SMEM_BYTES);
    reservoir_kernel<<<NCTA, NTHR, SMEM_BYTES>>>(x, s0, Win, What, (float*)d_out);
}